// round 8
// baseline (speedup 1.0000x reference)
#include <cuda_runtime.h>
#include <cuda_fp16.h>
#include <cstdint>
#include <cstddef>

#define BSZ   8192
#define DIMN  100
#define NSTEP 49
#define WH    256
#define RRATE 0.05f
#define KP1   112              // padded K for K=100 operands

// ---------------- device scratch (static, no allocations) ----------------
__device__ float g_volpre[(size_t)NSTEP * BSZ * DIMN]; // 160.6 MB
__device__ float g_Sbuf[2][BSZ * DIMN];
__device__ float g_grad[BSZ * DIMN];
__device__ float g_vbuf[2][BSZ];
__device__ float g_stoch[BSZ];
__device__ float g_err[BSZ];
// packed dual-MLP activations (hi/lo fp16), [16384][256]
__device__ __align__(16) __half g_hA_h[(size_t)2 * BSZ * WH];
__device__ __align__(16) __half g_hA_l[(size_t)2 * BSZ * WH];
__device__ __align__(16) __half g_hB_h[(size_t)2 * BSZ * WH];
__device__ __align__(16) __half g_hB_l[(size_t)2 * BSZ * WH];
// pre-split weights, [N][K] K-major
__device__ __align__(16) __half g_Wgt_in_h[WH * KP1], g_Wgt_in_l[WH * KP1];
__device__ __align__(16) __half g_Wvt_in_h[WH * KP1], g_Wvt_in_l[WH * KP1];
__device__ __align__(16) __half g_Wgt_h_h[3 * WH * WH], g_Wgt_h_l[3 * WH * WH];
__device__ __align__(16) __half g_Wvt_h_h[3 * WH * WH], g_Wvt_h_l[3 * WH * WH];
__device__ __align__(16) __half g_Wgt_out_h[DIMN * WH], g_Wgt_out_l[DIMN * WH];
__device__ __align__(16) __half g_Vt_h[DIMN * KP1],    g_Vt_l[DIMN * KP1];

// ---------------- helpers ----------------
__device__ __forceinline__ uint32_t smem_u32(const void* p) {
    uint32_t a;
    asm("{ .reg .u64 t; cvta.to.shared.u64 t, %1; cvt.u32.u64 %0, t; }" : "=r"(a) : "l"(p));
    return a;
}
__device__ __forceinline__ void split2(float x0, float x1, uint32_t& h, uint32_t& l) {
    __half2 hh = __floats2half2_rn(x0, x1);
    float2 hf = __half22float2(hh);
    __half2 ll = __floats2half2_rn(x0 - hf.x, x1 - hf.y);
    h = *reinterpret_cast<uint32_t*>(&hh);
    l = *reinterpret_cast<uint32_t*>(&ll);
}
__device__ __forceinline__ void mma16(float d[4], const uint32_t a[4],
                                      uint32_t b0, uint32_t b1) {
    asm volatile(
        "mma.sync.aligned.m16n8k16.row.col.f32.f16.f16.f32 "
        "{%0,%1,%2,%3}, {%4,%5,%6,%7}, {%8,%9}, {%0,%1,%2,%3};"
        : "+f"(d[0]), "+f"(d[1]), "+f"(d[2]), "+f"(d[3])
        : "r"(a[0]), "r"(a[1]), "r"(a[2]), "r"(a[3]), "r"(b0), "r"(b1));
}
__device__ __forceinline__ void ldm4(uint32_t r[4], uint32_t addr) {
    asm volatile("ldmatrix.sync.aligned.m8n8.x4.shared.b16 {%0,%1,%2,%3}, [%4];"
                 : "=r"(r[0]), "=r"(r[1]), "=r"(r[2]), "=r"(r[3]) : "r"(addr));
}

// smem layout per buffer: rows of 16 halves (32B data), row stride 48B
#define A_LO_OFF  6144
#define B_HI_OFF  12288
#define B_LO_OFF  18432
#define BUF_BYTES 24576
#define DYN_SMEM  (2 * BUF_BYTES)        // 49152

// ========== mma.sync fp16 (3x-split) GEMM, conversion-free mainloop ==========
// A: either float (Af, split on the fly; used for layer-1/volpre) or packed (Ahi/Alo).
// B: always pre-split packed halves. Output: float (Cf) or packed (Chi/Clo).
// CTA 128x128, BK=16, 8 warps (warp 32x64), 2 CTAs/SM.
__global__ __launch_bounds__(256, 2)
void gemm_mma(const float* __restrict__ Af,
              const __half* __restrict__ Ahi, const __half* __restrict__ Alo,
              const __half* __restrict__ Bhi0, const __half* __restrict__ Blo0,
              const __half* __restrict__ Bhi1, const __half* __restrict__ Blo1,
              const float* __restrict__ bias0, const float* __restrict__ bias1,
              const float* __restrict__ w00, const float* __restrict__ w01,
              const float* __restrict__ tg, int tIdx,
              float* __restrict__ Cf, __half* __restrict__ Chi, __half* __restrict__ Clo,
              int N, int K, int KP, int relu, int halfBlocks, int wrapA)
{
    extern __shared__ uint32_t smw[];
    char* smc = (char*)smw;
    const uint32_t smemBase = smem_u32(smw);

    const int tid    = threadIdx.x;
    const int lane   = tid & 31;
    const int wid    = tid >> 5;
    const int warp_m = wid & 3;
    const int warp_n = wid >> 2;
    const int mBase  = blockIdx.y * 128;
    const int nBase  = blockIdx.x * 128;
    const bool hiH   = (int)blockIdx.y >= halfBlocks;
    const __half* Bhi = hiH ? Bhi1 : Bhi0;
    const __half* Blo = hiH ? Blo1 : Blo0;
    const float* bias = hiH ? bias1 : bias0;
    const float* w0   = hiH ? w01   : w00;

    const int qrow = lane >> 2;
    const int qk   = lane & 3;

    float acc[2][8][4];
#pragma unroll
    for (int i = 0; i < 2; ++i)
#pragma unroll
        for (int j = 0; j < 8; ++j)
#pragma unroll
            for (int q = 0; q < 4; ++q) acc[i][j][q] = 0.f;

    // packed-load indices: 2 threads per row, 8 halves each
    const int rP  = tid >> 1;                 // 0..127
    const int kg  = (tid & 1) << 3;           // 0 or 8
    const int arP = mBase + rP;
    const int gnP = nBase + rP;
    // float-A indices
    const int r0  = tid >> 2;
    const int r1  = r0 + 64;
    const int c40 = (tid & 3) << 2;
    int ar0 = mBase + r0, ar1 = mBase + r1;
    if (wrapA) { ar0 &= (BSZ - 1); ar1 &= (BSZ - 1); }

    // ldmatrix offsets
    const int l15 = lane & 15;
    const int lc  = (lane >> 4) << 4;
    const uint32_t offA0 = (uint32_t)(warp_m * 32 + l15) * 48 + lc;
    const uint32_t offA1 = offA0 + 16 * 48;
    const uint32_t offB  = (uint32_t)B_HI_OFF + (uint32_t)(warp_n * 64 + l15) * 48 + lc;

    const int nChunks = KP >> 4;

    float4 av0, av1;
    uint4 pa0, pa1, pb0, pb1;
    auto prefetch = [&](int kc) {
        const int kh = (kc << 4) + kg;        // half offset within padded row
        if (Af) {
            const int gc = (kc << 4) + c40;
            av0 = av1 = make_float4(0.f, 0.f, 0.f, 0.f);
            if (gc < K) {
                av0 = *(const float4*)(Af + (size_t)ar0 * K + gc);
                av1 = *(const float4*)(Af + (size_t)ar1 * K + gc);
            }
        } else {
            pa0 = *(const uint4*)(Ahi + (size_t)arP * KP + kh);
            pa1 = *(const uint4*)(Alo + (size_t)arP * KP + kh);
        }
        if (gnP < N) {
            pb0 = *(const uint4*)(Bhi + (size_t)gnP * KP + kh);
            pb1 = *(const uint4*)(Blo + (size_t)gnP * KP + kh);
        } else {
            pb0 = pb1 = make_uint4(0, 0, 0, 0);
        }
    };
    auto store = [&](int b) {
        char* buf = smc + b * BUF_BYTES;
        if (Af) {
            const uint32_t rowOff0 = (uint32_t)r0 * 48 + c40 * 2;
            const uint32_t rowOff1 = (uint32_t)r1 * 48 + c40 * 2;
            uint32_t h0, l0, h1, l1;
            split2(av0.x, av0.y, h0, l0); split2(av0.z, av0.w, h1, l1);
            *(uint2*)(buf + rowOff0)            = make_uint2(h0, h1);
            *(uint2*)(buf + A_LO_OFF + rowOff0) = make_uint2(l0, l1);
            split2(av1.x, av1.y, h0, l0); split2(av1.z, av1.w, h1, l1);
            *(uint2*)(buf + rowOff1)            = make_uint2(h0, h1);
            *(uint2*)(buf + A_LO_OFF + rowOff1) = make_uint2(l0, l1);
        } else {
            const uint32_t ro = (uint32_t)rP * 48 + kg * 2;
            *(uint4*)(buf + ro)            = pa0;
            *(uint4*)(buf + A_LO_OFF + ro) = pa1;
        }
        const uint32_t rb = (uint32_t)rP * 48 + kg * 2;
        *(uint4*)(buf + B_HI_OFF + rb) = pb0;
        *(uint4*)(buf + B_LO_OFF + rb) = pb1;
    };

    prefetch(0);
    store(0);

    for (int kc = 0; kc < nChunks; ++kc) {
        __syncthreads();
        const bool more = (kc + 1 < nChunks);
        if (more) prefetch(kc + 1);

        const uint32_t base = smemBase + (kc & 1) * BUF_BYTES;

        uint32_t ax0[4], ax1[4], bb[4][4];
        // pass 1: Ah * Bh
        ldm4(ax0, base + offA0);
        ldm4(ax1, base + offA1);
#pragma unroll
        for (int t = 0; t < 4; ++t) ldm4(bb[t], base + offB + t * (16 * 48));
#pragma unroll
        for (int t = 0; t < 4; ++t) {
            mma16(acc[0][2 * t],     ax0, bb[t][0], bb[t][2]);
            mma16(acc[1][2 * t],     ax1, bb[t][0], bb[t][2]);
            mma16(acc[0][2 * t + 1], ax0, bb[t][1], bb[t][3]);
            mma16(acc[1][2 * t + 1], ax1, bb[t][1], bb[t][3]);
        }
        // pass 2: Al * Bh (bh resident)
        {
            uint32_t al0[4], al1[4];
            ldm4(al0, base + offA0 + A_LO_OFF);
            ldm4(al1, base + offA1 + A_LO_OFF);
#pragma unroll
            for (int t = 0; t < 4; ++t) {
                mma16(acc[0][2 * t],     al0, bb[t][0], bb[t][2]);
                mma16(acc[1][2 * t],     al1, bb[t][0], bb[t][2]);
                mma16(acc[0][2 * t + 1], al0, bb[t][1], bb[t][3]);
                mma16(acc[1][2 * t + 1], al1, bb[t][1], bb[t][3]);
            }
        }
        // pass 3: Ah * Bl
#pragma unroll
        for (int t = 0; t < 4; ++t)
            ldm4(bb[t], base + offB + (B_LO_OFF - B_HI_OFF) + t * (16 * 48));
#pragma unroll
        for (int t = 0; t < 4; ++t) {
            mma16(acc[0][2 * t],     ax0, bb[t][0], bb[t][2]);
            mma16(acc[1][2 * t],     ax1, bb[t][0], bb[t][2]);
            mma16(acc[0][2 * t + 1], ax0, bb[t][1], bb[t][3]);
            mma16(acc[1][2 * t + 1], ax1, bb[t][1], bb[t][3]);
        }

        if (more) store((kc + 1) & 1);
    }

    // ---------------- epilogue ----------------
    const float tval = w0 ? __ldg(tg + tIdx) : 0.f;
#pragma unroll
    for (int jn = 0; jn < 8; ++jn) {
        int c = nBase + warp_n * 64 + jn * 8 + 2 * qk;
        if (c >= N) continue;
        float b0e = 0.f, b1e = 0.f;
        if (bias) { b0e = __ldg(bias + c); b1e = __ldg(bias + c + 1); }
        if (w0)   { b0e += tval * __ldg(w0 + c); b1e += tval * __ldg(w0 + c + 1); }
#pragma unroll
        for (int im = 0; im < 2; ++im) {
            int r = mBase + warp_m * 32 + im * 16 + qrow;
            float o00 = acc[im][jn][0] + b0e, o01 = acc[im][jn][1] + b1e;
            float o10 = acc[im][jn][2] + b0e, o11 = acc[im][jn][3] + b1e;
            if (relu) {
                o00 = fmaxf(o00, 0.f); o01 = fmaxf(o01, 0.f);
                o10 = fmaxf(o10, 0.f); o11 = fmaxf(o11, 0.f);
            }
            if (Cf) {
                *(float2*)(Cf + (size_t)r * N + c)       = make_float2(o00, o01);
                *(float2*)(Cf + (size_t)(r + 8) * N + c) = make_float2(o10, o11);
            } else {
                uint32_t h, l;
                split2(o00, o01, h, l);
                *(uint32_t*)(Chi + (size_t)r * N + c) = h;
                *(uint32_t*)(Clo + (size_t)r * N + c) = l;
                split2(o10, o11, h, l);
                *(uint32_t*)(Chi + (size_t)(r + 8) * N + c) = h;
                *(uint32_t*)(Clo + (size_t)(r + 8) * N + c) = l;
            }
        }
    }
}

// ---------------- one-time weight prepack (transpose + hi/lo split) ----------
#define N_IN   (WH * KP1)        // 28672
#define N_HID  (3 * WH * WH)     // 196608
#define N_OUT  (DIMN * WH)       // 25600
#define N_VT   (DIMN * KP1)      // 11200
#define PP_TOTAL (2 * N_IN + 2 * N_HID + N_OUT + N_VT)
__global__ void prepack_all(const float* __restrict__ Wg_in, const float* __restrict__ Wv_in,
                            const float* __restrict__ Wg_h,  const float* __restrict__ Wv_h,
                            const float* __restrict__ Wg_out, const float* __restrict__ Vm)
{
    for (int i = blockIdx.x * blockDim.x + threadIdx.x; i < PP_TOTAL;
         i += gridDim.x * blockDim.x) {
        int j = i;
        float v;
        __half *dh, *dl;
        if (j < N_IN) {                        // Wg_in: [256][112] <- src[(k+1)*256+n]
            int n = j / KP1, k = j % KP1;
            v = (k < DIMN) ? Wg_in[(size_t)(k + 1) * WH + n] : 0.f;
            dh = g_Wgt_in_h; dl = g_Wgt_in_l;
        } else if ((j -= N_IN) < N_IN) {       // Wv_in
            int n = j / KP1, k = j % KP1;
            v = (k < DIMN) ? Wv_in[(size_t)(k + 1) * WH + n] : 0.f;
            dh = g_Wvt_in_h; dl = g_Wvt_in_l;
        } else if ((j -= N_IN) < N_HID) {      // Wg_h: [3][256][256]
            int l = j / 65536, r = j % 65536;
            int n = r / WH, k = r % WH;
            v = Wg_h[(size_t)l * 65536 + (size_t)k * WH + n];
            dh = g_Wgt_h_h; dl = g_Wgt_h_l;
        } else if ((j -= N_HID) < N_HID) {     // Wv_h
            int l = j / 65536, r = j % 65536;
            int n = r / WH, k = r % WH;
            v = Wv_h[(size_t)l * 65536 + (size_t)k * WH + n];
            dh = g_Wvt_h_h; dl = g_Wvt_h_l;
        } else if ((j -= N_HID) < N_OUT) {     // Wg_out: [100][256] <- src[k*100+n]
            int n = j / WH, k = j % WH;
            v = Wg_out[(size_t)k * DIMN + n];
            dh = g_Wgt_out_h; dl = g_Wgt_out_l;
        } else {                               // Vm: [100][112] <- src[n*100+k]
            j -= N_OUT;
            int n = j / KP1, k = j % KP1;
            v = (k < DIMN) ? Vm[(size_t)n * DIMN + k] : 0.f;
            dh = g_Vt_h; dl = g_Vt_l;
        }
        __half h = __float2half_rn(v);
        __half l = __float2half_rn(v - __half2float(h));
        dh[j] = h; dl[j] = l;
    }
}

// ---------------- fused GEMV (packed input) + error ----------
__global__ __launch_bounds__(256) void gemv_err(
    const __half* __restrict__ Hhi, const __half* __restrict__ Hlo,
    const float* __restrict__ w, const float* __restrict__ b,
    const float* __restrict__ vOld, const float* __restrict__ stoch,
    const float* __restrict__ tg, int i,
    float* __restrict__ vNew, float* __restrict__ err, int doErr)
{
    __shared__ __align__(16) float ws[WH];
    ws[threadIdx.x] = w[threadIdx.x];
    __syncthreads();
    int warp = threadIdx.x >> 5, lane = threadIdx.x & 31;
    int row = blockIdx.x * 8 + warp;
    uint4 hv = *(const uint4*)(Hhi + (size_t)row * WH + lane * 8);
    uint4 lv = *(const uint4*)(Hlo + (size_t)row * WH + lane * 8);
    const __half2* h2 = (const __half2*)&hv;
    const __half2* l2 = (const __half2*)&lv;
    float acc = 0.f;
#pragma unroll
    for (int q = 0; q < 4; ++q) {
        float2 hf = __half22float2(h2[q]);
        float2 lf = __half22float2(l2[q]);
        acc += (hf.x + lf.x) * ws[lane * 8 + q * 2]
             + (hf.y + lf.y) * ws[lane * 8 + q * 2 + 1];
    }
#pragma unroll
    for (int o = 16; o; o >>= 1) acc += __shfl_xor_sync(0xffffffffu, acc, o);
    if (lane == 0) {
        float v = acc + b[0];
        vNew[row] = v;
        if (doErr) {
            float h = tg[i + 1] - tg[i];
            float e = v - vOld[row] * (1.f + RRATE * h) - stoch[row];
            err[row] += e * e;
        }
    }
}

// ---------------- step: vol, stoch_int, S update ----------------
__global__ __launch_bounds__(256) void step_kernel(
    const float* __restrict__ S_old, const float* __restrict__ vp,
    const float* __restrict__ grad, const float* __restrict__ tg, int i,
    float* __restrict__ S_new, float* __restrict__ stoch)
{
    int warp = threadIdx.x >> 5, lane = threadIdx.x & 31;
    int b = blockIdx.x * 8 + warp;
    float h  = tg[i + 1] - tg[i];
    float sq = sqrtf(h);
    float rh = RRATE * h;
    const float* Sr = S_old + (size_t)b * DIMN;
    const float* vr = vp   + (size_t)b * DIMN;
    const float* gr = grad + (size_t)b * DIMN;
    float acc = 0.f;
    for (int d = lane; d < DIMN; d += 32) {
        float s   = Sr[d];
        float vol = s * (vr[d] * sq);
        acc += gr[d] * vol;
        S_new[(size_t)b * DIMN + d] = s + rh * s + vol;
    }
#pragma unroll
    for (int o = 16; o; o >>= 1) acc += __shfl_xor_sync(0xffffffffu, acc, o);
    if (lane == 0) stoch[b] = acc;
}

// ---------------- output packing: [v_f | S_f | error] ----------------
__global__ void pack_kernel(const float* __restrict__ v, const float* __restrict__ S,
                            const float* __restrict__ err, float* __restrict__ out)
{
    int i = blockIdx.x * 256 + threadIdx.x;
    if (i < BSZ * DIMN) out[BSZ + i] = S[i];
    if (i < BSZ) {
        out[i] = v[i];
        out[BSZ + BSZ * DIMN + i] = err[i];
    }
}

extern "C" void kernel_launch(void* const* d_in, const int* in_sizes, int n_in,
                              void* d_out, int out_size)
{
    const float* S0     = (const float*)d_in[0];
    const float* dW     = (const float*)d_in[1];
    const float* tg     = (const float*)d_in[2];
    const float* Vm     = (const float*)d_in[3];
    const float* Wg_in  = (const float*)d_in[4];
    const float* bg_in  = (const float*)d_in[5];
    const float* Wg_h   = (const float*)d_in[6];
    const float* bg_h   = (const float*)d_in[7];
    const float* Wg_out = (const float*)d_in[8];
    const float* bg_out = (const float*)d_in[9];
    const float* Wv_in  = (const float*)d_in[10];
    const float* bv_in  = (const float*)d_in[11];
    const float* Wv_h   = (const float*)d_in[12];
    const float* bv_h   = (const float*)d_in[13];
    const float* Wv_out = (const float*)d_in[14];
    const float* bv_out = (const float*)d_in[15];

    float *volpre, *Sb, *grad, *vb, *stoch, *err;
    __half *hAh, *hAl, *hBh, *hBl;
    __half *Wgt_in_h, *Wgt_in_l, *Wvt_in_h, *Wvt_in_l;
    __half *Wgt_h_h, *Wgt_h_l, *Wvt_h_h, *Wvt_h_l;
    __half *Wgt_out_h, *Wgt_out_l, *Vt_h, *Vt_l;
    cudaGetSymbolAddress((void**)&volpre, g_volpre);
    cudaGetSymbolAddress((void**)&Sb,     g_Sbuf);
    cudaGetSymbolAddress((void**)&grad,   g_grad);
    cudaGetSymbolAddress((void**)&vb,     g_vbuf);
    cudaGetSymbolAddress((void**)&stoch,  g_stoch);
    cudaGetSymbolAddress((void**)&err,    g_err);
    cudaGetSymbolAddress((void**)&hAh, g_hA_h);  cudaGetSymbolAddress((void**)&hAl, g_hA_l);
    cudaGetSymbolAddress((void**)&hBh, g_hB_h);  cudaGetSymbolAddress((void**)&hBl, g_hB_l);
    cudaGetSymbolAddress((void**)&Wgt_in_h, g_Wgt_in_h);
    cudaGetSymbolAddress((void**)&Wgt_in_l, g_Wgt_in_l);
    cudaGetSymbolAddress((void**)&Wvt_in_h, g_Wvt_in_h);
    cudaGetSymbolAddress((void**)&Wvt_in_l, g_Wvt_in_l);
    cudaGetSymbolAddress((void**)&Wgt_h_h, g_Wgt_h_h);
    cudaGetSymbolAddress((void**)&Wgt_h_l, g_Wgt_h_l);
    cudaGetSymbolAddress((void**)&Wvt_h_h, g_Wvt_h_h);
    cudaGetSymbolAddress((void**)&Wvt_h_l, g_Wvt_h_l);
    cudaGetSymbolAddress((void**)&Wgt_out_h, g_Wgt_out_h);
    cudaGetSymbolAddress((void**)&Wgt_out_l, g_Wgt_out_l);
    cudaGetSymbolAddress((void**)&Vt_h, g_Vt_h);
    cudaGetSymbolAddress((void**)&Vt_l, g_Vt_l);

    float* Sbuf0 = Sb;
    float* Sbuf1 = Sb + (size_t)BSZ * DIMN;
    float* vA = vb;
    float* vBp = vb + BSZ;

    // launch 0: prepack weights (transpose + hi/lo split, padded)
    prepack_all<<<512, 256>>>(Wg_in, Wv_in, Wg_h, Wv_h, Wg_out, Vm);

    // launch 1: volpre = dW @ V^T  (float A path, packed V, float out)
    {
        dim3 grid(1, (NSTEP * BSZ) / 128);
        gemm_mma<<<grid, 256, DYN_SMEM>>>(dW, nullptr, nullptr,
            Vt_h, Vt_l, Vt_h, Vt_l, nullptr, nullptr, nullptr, nullptr,
            nullptr, 0, volpre, nullptr, nullptr,
            DIMN, DIMN, KP1, 0, 1 << 30, 0);
    }

    auto dual_trunk = [&](const float* S, int tIdx) {
        dim3 grid(2, 128);
        // L1: float A (wrap), packed dual weights, packed out -> hA
        gemm_mma<<<grid, 256, DYN_SMEM>>>(S, nullptr, nullptr,
            Wgt_in_h, Wgt_in_l, Wvt_in_h, Wvt_in_l, bg_in, bv_in, Wg_in, Wv_in,
            tg, tIdx, nullptr, hAh, hAl, WH, DIMN, KP1, 1, 64, 1);
        // L2..L4: packed A, packed out, ping-pong hA/hB
        gemm_mma<<<grid, 256, DYN_SMEM>>>(nullptr, hAh, hAl,
            Wgt_h_h, Wgt_h_l, Wvt_h_h, Wvt_h_l, bg_h, bv_h, nullptr, nullptr,
            nullptr, 0, nullptr, hBh, hBl, WH, WH, WH, 1, 64, 0);
        gemm_mma<<<grid, 256, DYN_SMEM>>>(nullptr, hBh, hBl,
            Wgt_h_h + 65536, Wgt_h_l + 65536, Wvt_h_h + 65536, Wvt_h_l + 65536,
            bg_h + WH, bv_h + WH, nullptr, nullptr,
            nullptr, 0, nullptr, hAh, hAl, WH, WH, WH, 1, 64, 0);
        gemm_mma<<<grid, 256, DYN_SMEM>>>(nullptr, hAh, hAl,
            Wgt_h_h + 2 * 65536, Wgt_h_l + 2 * 65536, Wvt_h_h + 2 * 65536, Wvt_h_l + 2 * 65536,
            bg_h + 2 * WH, bv_h + 2 * WH, nullptr, nullptr,
            nullptr, 0, nullptr, hBh, hBl, WH, WH, WH, 1, 64, 0);
    };
    auto grad_gemm = [&]() {
        dim3 grid(1, 64);
        gemm_mma<<<grid, 256, DYN_SMEM>>>(nullptr, hBh, hBl,
            Wgt_out_h, Wgt_out_l, Wgt_out_h, Wgt_out_l, bg_out, bg_out,
            nullptr, nullptr, nullptr, 0, grad, nullptr, nullptr,
            DIMN, WH, WH, 0, 1 << 30, 0);
    };

    // launches 2-5: dual trunk on [t0, S0]
    dual_trunk(S0, 0);
    grad_gemm();                                                 // grad_0
    gemv_err<<<BSZ / 8, 256>>>(hBh + (size_t)BSZ * WH, hBl + (size_t)BSZ * WH,
                               Wv_out, bv_out, nullptr, nullptr, tg, 0, vA, err, 0);

    cudaMemsetAsync(err, 0, BSZ * sizeof(float));

    const float* Scur = S0;
    float* vOld = vA;
    float* vNew = vBp;
    int sflip = 0;
    for (int i = 0; i < NSTEP; ++i) {
        float* Snew = sflip ? Sbuf1 : Sbuf0;
        step_kernel<<<BSZ / 8, 256>>>(Scur, volpre + (size_t)i * BSZ * DIMN,
                                      grad, tg, i, Snew, stoch);
        dual_trunk(Snew, i + 1);
        grad_gemm();                                             // grad_{i+1}
        gemv_err<<<BSZ / 8, 256>>>(hBh + (size_t)BSZ * WH, hBl + (size_t)BSZ * WH,
                                   Wv_out, bv_out, vOld, stoch, tg, i, vNew, err, 1);
        Scur = Snew; sflip ^= 1;
        float* t = vOld; vOld = vNew; vNew = t;
    }

    // output: [v_f (8192) | S_f (8192*100) | error (8192)]
    pack_kernel<<<(BSZ * DIMN) / 256, 256>>>(vOld, Scur, err, (float*)d_out);
}